// round 6
// baseline (speedup 1.0000x reference)
#include <cuda_runtime.h>
#include <cuda_bf16.h>

// DifferentiableSMMPC: u = 0 is a fixed point of the reference iteration
// (Q_u = 2*R*0 = 0 -> k = 0 -> u stays 0), so the output u_traj[:, 0] is an
// exact (2048, 128) fp32 zero block; the only work is zero-filling d_out.
//
// R2: grid=256x256, guarded        -> dur 4.93 (kernel 3.74)
// R3: cudaMemsetAsync graph node   -> dur 6.88 (reverted)
// R4: grid=128x512, guarded        -> dur 4.58 (kernel 3.46)  <- best shape
// R5: grid= 64x512x2, unguarded    -> dur 4.58 (kernel 3.58)  <- fewer CTAs worse
// R6: merge winners: grid=128x512, unguarded, 1 STG.128/thread.
//     Minimal SASS body (S2R, IMAD, STG.128, EXIT). At the launch floor:
//     dur = kernel floor (~3.4us) + ~1.1us graph-replay overhead; the 1 MiB
//     of stores itself is <0.2us (DRAM 0.0% in every profile).

__global__ __launch_bounds__(512, 1)
void smmpc_zero_fill_exact(float4* __restrict__ out) {
    out[blockIdx.x * 512 + threadIdx.x] = make_float4(0.f, 0.f, 0.f, 0.f);
}

__global__ void smmpc_zero_fill_guarded(float* __restrict__ out, int n) {
    int i = blockIdx.x * blockDim.x + threadIdx.x;
    if (i < n) out[i] = 0.f;
}

extern "C" void kernel_launch(void* const* d_in, const int* in_sizes, int n_in,
                              void* d_out, int out_size) {
    (void)d_in; (void)in_sizes; (void)n_in;

    float* out = (float*)d_out;
    int n_vec4 = out_size / 4;            // 65536 for the (2048,128) output

    if ((out_size & 3) == 0 && n_vec4 % 512 == 0) {
        int blocks = n_vec4 / 512;        // 128 -> single wave, no guard
        smmpc_zero_fill_exact<<<blocks, 512>>>((float4*)out);
    } else {
        smmpc_zero_fill_guarded<<<(out_size + 511) / 512, 512>>>(out, out_size);
    }
}